// round 3
// baseline (speedup 1.0000x reference)
#include <cuda_runtime.h>

// Non-local block = attention, head_dim=32, N=6400, B=2, fp32.
// R1: packed fma.rn.f32x2 (sm_103a dual-rate fp32) in all three stages.

#define BATCH 2
#define CH 64
#define DI 32
#define NP 6400
#define TQ 128
#define TK 64
#define SPLITS 5
#define KEYS_PER_SPLIT (NP / SPLITS)   // 1280

typedef unsigned long long u64;

__device__ __forceinline__ u64 f2fma(u64 a, u64 b, u64 c) {
    u64 d; asm("fma.rn.f32x2 %0,%1,%2,%3;" : "=l"(d) : "l"(a), "l"(b), "l"(c)); return d;
}
__device__ __forceinline__ u64 f2mul(u64 a, u64 b) {
    u64 d; asm("mul.rn.f32x2 %0,%1,%2;" : "=l"(d) : "l"(a), "l"(b)); return d;
}
__device__ __forceinline__ u64 f2pack(float x) {
    u64 d; asm("mov.b64 %0,{%1,%2};" : "=l"(d) : "f"(x), "f"(x)); return d;
}
__device__ __forceinline__ float f2hadd(u64 a) {
    float lo, hi; asm("mov.b64 {%0,%1},%2;" : "=f"(lo), "=f"(hi) : "l"(a)); return lo + hi;
}

__device__ float g_Q[BATCH * NP * DI];
__device__ float g_K[BATCH * NP * DI];
__device__ float g_V[BATCH * NP * DI];
__device__ float g_acc[BATCH * SPLITS * NP * DI];
__device__ float g_mp[BATCH * SPLITS * NP];
__device__ float g_lp[BATCH * SPLITS * NP];

// ---------------------------------------------------------------------------
// Stage 1: Q/K/V projection. 384 threads: warpgroup 0->theta, 1->phi, 2->g.
// ---------------------------------------------------------------------------
#define PT 384
__global__ void __launch_bounds__(PT) proj_kernel(
    const float* __restrict__ x,
    const float* __restrict__ theta_w,
    const float* __restrict__ phi_w,
    const float* __restrict__ gw)
{
    __shared__ __align__(16) float xs[CH * TQ];        // [c][p]
    __shared__ __align__(16) float wsT[3 * CH * DI];   // transposed [c][i]

    const int b   = blockIdx.y;
    const int n0  = blockIdx.x * TQ;
    const int tid = threadIdx.x;
    const int wg  = tid >> 7;       // 0..2
    const int wt  = tid & 127;      // position within tile

    const float* wsrc = (wg == 0) ? theta_w : (wg == 1) ? phi_w : gw;
    float*       dst  = (wg == 0) ? g_Q     : (wg == 1) ? g_K   : g_V;

    // transpose weights into smem: w[i][c] -> wsT[c][i]
    for (int idx = wt; idx < DI * CH; idx += 128) {
        int i = idx / CH, c = idx % CH;
        wsT[wg * CH * DI + c * DI + i] = wsrc[idx];
    }
    // x tile cooperative load
    const float* xb = x + b * CH * NP + n0;
    for (int idx = tid; idx < CH * TQ; idx += PT) {
        int c = idx >> 7, p = idx & 127;
        xs[idx] = xb[c * NP + p];
    }
    __syncthreads();

    u64 acc2[16];
    #pragma unroll
    for (int i = 0; i < 16; i++) acc2[i] = 0ull;

    const float* wp = wsT + wg * CH * DI;
    #pragma unroll 4
    for (int c = 0; c < CH; c++) {
        u64 x2 = f2pack(xs[c * TQ + wt]);
        const u64* w2 = (const u64*)(wp + c * DI);
        #pragma unroll
        for (int i2 = 0; i2 < 16; i2++)
            acc2[i2] = f2fma(w2[i2], x2, acc2[i2]);
    }

    ulonglong2* dp = (ulonglong2*)(dst + (b * NP + n0 + wt) * DI);
    #pragma unroll
    for (int i4 = 0; i4 < 8; i4++)
        dp[i4] = make_ulonglong2(acc2[2 * i4], acc2[2 * i4 + 1]);
}

// ---------------------------------------------------------------------------
// Stage 2: split-K flash attention, f32x2 math. Thread = 1 query.
// grid: (N/TQ, SPLITS, BATCH), single wave (500 blocks, 4 blocks/SM).
// ---------------------------------------------------------------------------
__global__ void __launch_bounds__(TQ, 4) attn_kernel()
{
    __shared__ __align__(16) float ks[TK * DI];
    __shared__ __align__(16) float vs[TK * DI];

    const int b     = blockIdx.z;
    const int split = blockIdx.y;
    const int tid   = threadIdx.x;
    const int n     = blockIdx.x * TQ + tid;

    u64 q2[16];
    {
        const ulonglong2* Qp = (const ulonglong2*)(g_Q + (b * NP + n) * DI);
        #pragma unroll
        for (int d8 = 0; d8 < 8; d8++) {
            ulonglong2 t = Qp[d8];
            q2[2 * d8] = t.x; q2[2 * d8 + 1] = t.y;
        }
    }

    u64 acc2[16];
    #pragma unroll
    for (int i = 0; i < 16; i++) acc2[i] = 0ull;
    float m = -1e30f, l = 0.f;

    const int k0base = split * KEYS_PER_SPLIT;
    const float4* Kb = (const float4*)(g_K + b * NP * DI);
    const float4* Vb = (const float4*)(g_V + b * NP * DI);

    for (int kt = 0; kt < KEYS_PER_SPLIT; kt += TK) {
        const int krow0 = k0base + kt;
        #pragma unroll
        for (int r = 0; r < 4; r++) {
            int idx = r * TQ + tid;
            ((float4*)ks)[idx] = Kb[krow0 * (DI / 4) + idx];
            ((float4*)vs)[idx] = Vb[krow0 * (DI / 4) + idx];
        }
        __syncthreads();

        #pragma unroll 1
        for (int j0 = 0; j0 < TK; j0 += 16) {
            float s[16];
            #pragma unroll
            for (int jj = 0; jj < 16; jj++) {
                const ulonglong2* kr = (const ulonglong2*)(ks + (j0 + jj) * DI);
                u64 s2 = 0ull;
                #pragma unroll
                for (int d8 = 0; d8 < 8; d8++) {
                    ulonglong2 kk = kr[d8];
                    s2 = f2fma(q2[2 * d8],     kk.x, s2);
                    s2 = f2fma(q2[2 * d8 + 1], kk.y, s2);
                }
                s[jj] = f2hadd(s2);
            }
            float cm = s[0];
            #pragma unroll
            for (int jj = 1; jj < 16; jj++) cm = fmaxf(cm, s[jj]);
            if (cm > m) {
                float scale = __expf(m - cm);
                m = cm;
                l *= scale;
                u64 sc2 = f2pack(scale);
                #pragma unroll
                for (int i = 0; i < 16; i++) acc2[i] = f2mul(acc2[i], sc2);
            }
            #pragma unroll
            for (int jj = 0; jj < 16; jj++) {
                float p = __expf(s[jj] - m);
                l += p;
                u64 p2 = f2pack(p);
                const ulonglong2* vr = (const ulonglong2*)(vs + (j0 + jj) * DI);
                #pragma unroll
                for (int d8 = 0; d8 < 8; d8++) {
                    ulonglong2 vv = vr[d8];
                    acc2[2 * d8]     = f2fma(p2, vv.x, acc2[2 * d8]);
                    acc2[2 * d8 + 1] = f2fma(p2, vv.y, acc2[2 * d8 + 1]);
                }
            }
        }
        __syncthreads();
    }

    const int pidx = (b * SPLITS + split) * NP + n;
    ulonglong2* ap = (ulonglong2*)(g_acc + (long long)pidx * DI);
    #pragma unroll
    for (int d8 = 0; d8 < 8; d8++)
        ap[d8] = make_ulonglong2(acc2[2 * d8], acc2[2 * d8 + 1]);
    g_mp[pidx] = m;
    g_lp[pidx] = l;
}

// ---------------------------------------------------------------------------
// Stage 3: merge partials + output projection + residual.
// 256 threads: half 0 -> channels 0..31, half 1 -> channels 32..63.
// ---------------------------------------------------------------------------
#define MT 256
__global__ void __launch_bounds__(MT) merge_out_kernel(
    const float* __restrict__ x,
    const float* __restrict__ w_w,
    float* __restrict__ out)
{
    __shared__ __align__(16) float ws[CH * DI];
    const int b    = blockIdx.y;
    const int tid  = threadIdx.x;
    const int half = tid >> 7;
    const int qt   = tid & 127;
    const int n    = blockIdx.x * TQ + qt;

    for (int i = tid; i < CH * DI; i += MT) ws[i] = w_w[i];
    __syncthreads();

    float mv[SPLITS], lv[SPLITS];
    float M = -1e30f;
    #pragma unroll
    for (int s = 0; s < SPLITS; s++) {
        int pidx = (b * SPLITS + s) * NP + n;
        mv[s] = g_mp[pidx];
        lv[s] = g_lp[pidx];
        M = fmaxf(M, mv[s]);
    }

    float L = 0.f;
    u64 y2[16];
    #pragma unroll
    for (int i = 0; i < 16; i++) y2[i] = 0ull;

    #pragma unroll
    for (int s = 0; s < SPLITS; s++) {
        float w = __expf(mv[s] - M);
        L += lv[s] * w;
        u64 w2 = f2pack(w);
        const ulonglong2* ap = (const ulonglong2*)(g_acc + (long long)((b * SPLITS + s) * NP + n) * DI);
        #pragma unroll
        for (int d8 = 0; d8 < 8; d8++) {
            ulonglong2 a = ap[d8];
            y2[2 * d8]     = f2fma(w2, a.x, y2[2 * d8]);
            y2[2 * d8 + 1] = f2fma(w2, a.y, y2[2 * d8 + 1]);
        }
    }
    u64 inv2 = f2pack(1.f / L);
    #pragma unroll
    for (int i = 0; i < 16; i++) y2[i] = f2mul(y2[i], inv2);

    const float* xb = x + b * CH * NP + n;
    float* ob = out + b * CH * NP + n;
    const int c0 = half * 32;
    #pragma unroll 2
    for (int c = c0; c < c0 + 32; c++) {
        const u64* w2p = (const u64*)(ws + c * DI);
        u64 o2 = 0ull;
        #pragma unroll
        for (int i2 = 0; i2 < 16; i2++)
            o2 = f2fma(w2p[i2], y2[i2], o2);
        ob[c * NP] = xb[c * NP] + f2hadd(o2);
    }
}

// ---------------------------------------------------------------------------
extern "C" void kernel_launch(void* const* d_in, const int* in_sizes, int n_in,
                              void* d_out, int out_size)
{
    const float* x       = (const float*)d_in[0];
    const float* gw      = (const float*)d_in[1];
    const float* theta_w = (const float*)d_in[2];
    const float* phi_w   = (const float*)d_in[3];
    const float* w_w     = (const float*)d_in[4];
    float* out           = (float*)d_out;

    dim3 gp(NP / TQ, BATCH);
    proj_kernel<<<gp, PT>>>(x, theta_w, phi_w, gw);

    dim3 ga(NP / TQ, SPLITS, BATCH);
    attn_kernel<<<ga, TQ>>>();

    merge_out_kernel<<<gp, MT>>>(x, w_w, out);
}

// round 5
// speedup vs baseline: 2.5824x; 2.5824x over previous
#include <cuda_runtime.h>
#include <cuda_bf16.h>
#include <cstdint>

#define BATCH 2
#define CH 64
#define DI 32
#define NP 6400
#define SPL 2
#define KPS (NP / SPL)     // 3200 keys per split
#define KT 64              // keys per tile
#define NTL (KPS / KT)     // 50 tiles
#define QB 64              // queries per CTA

typedef uint32_t u32;
typedef unsigned long long u64;

// ---------------- scratch ----------------
__device__ __nv_bfloat16 g_Qh[BATCH * NP * DI], g_Ql[BATCH * NP * DI];
__device__ __nv_bfloat16 g_Kh[BATCH * NP * DI], g_Kl[BATCH * NP * DI];
__device__ __nv_bfloat16 g_Vh[BATCH * DI * NP], g_Vl[BATCH * DI * NP]; // [b][d][n]
__device__ float g_thn[BATCH * NP];
__device__ unsigned g_phimax[BATCH];
__device__ float g_acc[BATCH * SPL * NP * DI];
__device__ float g_lp[BATCH * SPL * NP];

// ---------------- helpers ----------------
__device__ __forceinline__ u64 f2fma(u64 a, u64 b, u64 c) {
    u64 d; asm("fma.rn.f32x2 %0,%1,%2,%3;" : "=l"(d) : "l"(a), "l"(b), "l"(c)); return d;
}
__device__ __forceinline__ float f2hadd(u64 a) {
    float lo, hi; asm("mov.b64 {%0,%1},%2;" : "=f"(lo), "=f"(hi) : "l"(a)); return lo + hi;
}
// pack two f32 -> bf16x2 (lo element = 'lo', hi element = 'hi')
__device__ __forceinline__ u32 pkbf(float hi, float lo) {
    u32 r; asm("cvt.rn.bf16x2.f32 %0,%1,%2;" : "=r"(r) : "f"(hi), "f"(lo)); return r;
}
__device__ __forceinline__ float bflo(u32 p) { return __uint_as_float(p << 16); }
__device__ __forceinline__ float bfhi(u32 p) { return __uint_as_float(p & 0xffff0000u); }

__device__ __forceinline__ void mma_bf16(float* c, const u32* a, u32 b0, u32 b1) {
    asm("mma.sync.aligned.m16n8k16.row.col.f32.bf16.bf16.f32 "
        "{%0,%1,%2,%3},{%4,%5,%6,%7},{%8,%9},{%0,%1,%2,%3};"
        : "+f"(c[0]), "+f"(c[1]), "+f"(c[2]), "+f"(c[3])
        : "r"(a[0]), "r"(a[1]), "r"(a[2]), "r"(a[3]), "r"(b0), "r"(b1));
}
__device__ __forceinline__ void cpa16(void* s, const void* g) {
    u32 sa; asm("{ .reg .u64 t; cvta.to.shared.u64 t,%1; cvt.u32.u64 %0,t; }" : "=r"(sa) : "l"(s));
    asm volatile("cp.async.cg.shared.global [%0],[%1],16;" :: "r"(sa), "l"(g) : "memory");
}

// ---------------------------------------------------------------------------
// Stage 1: projection -> Qh/Ql, Kh/Kl (bf16 hi/lo, [b][n][32]),
//          Vh/Vl transposed ([b][d][n]), theta norms, max phi norm.
// 384 threads: warpgroup 0=theta, 1=phi, 2=g.
// ---------------------------------------------------------------------------
#define PT 384
__global__ void __launch_bounds__(PT) proj_kernel(
    const float* __restrict__ x,
    const float* __restrict__ theta_w,
    const float* __restrict__ phi_w,
    const float* __restrict__ gw)
{
    __shared__ __align__(16) float xs[CH * 128];
    __shared__ __align__(16) float wsT[3 * CH * DI];

    const int b = blockIdx.y, n0 = blockIdx.x * 128, tid = threadIdx.x;
    const int wg = tid >> 7, wt = tid & 127;
    const float* wsrc = (wg == 0) ? theta_w : (wg == 1) ? phi_w : gw;

    for (int idx = wt; idx < DI * CH; idx += 128) {
        int i = idx / CH, c = idx % CH;
        wsT[wg * CH * DI + c * DI + i] = wsrc[idx];
    }
    const float* xb = x + b * CH * NP + n0;
    for (int idx = tid; idx < CH * 128; idx += PT)
        xs[idx] = xb[(idx >> 7) * NP + (idx & 127)];
    __syncthreads();

    u64 acc2[16];
    #pragma unroll
    for (int i = 0; i < 16; i++) acc2[i] = 0ull;
    const float* wp = wsT + wg * CH * DI;
    #pragma unroll 4
    for (int c = 0; c < CH; c++) {
        float xv = xs[c * 128 + wt];
        u64 x2; asm("mov.b64 %0,{%1,%1};" : "=l"(x2) : "f"(xv));
        const u64* w2 = (const u64*)(wp + c * DI);
        #pragma unroll
        for (int i2 = 0; i2 < 16; i2++) acc2[i2] = f2fma(w2[i2], x2, acc2[i2]);
    }
    float v[DI];
    #pragma unroll
    for (int i2 = 0; i2 < 16; i2++)
        asm("mov.b64 {%0,%1},%2;" : "=f"(v[2 * i2]), "=f"(v[2 * i2 + 1]) : "l"(acc2[i2]));

    const int n = n0 + wt;
    if (wg == 2) {                 // V transposed hi/lo
        #pragma unroll
        for (int i = 0; i < DI; i++) {
            __nv_bfloat16 h = __float2bfloat16(v[i]);
            g_Vh[(b * DI + i) * NP + n] = h;
            g_Vl[(b * DI + i) * NP + n] = __float2bfloat16(v[i] - __bfloat162float(h));
        }
    } else {
        __nv_bfloat16* hd = (wg == 0) ? g_Qh : g_Kh;
        __nv_bfloat16* ld = (wg == 0) ? g_Ql : g_Kl;
        float nrm = 0.f;
        u32 hb[16], lb[16];
        #pragma unroll
        for (int i2 = 0; i2 < 16; i2++) {
            float f0 = v[2 * i2], f1 = v[2 * i2 + 1];
            nrm = fmaf(f0, f0, fmaf(f1, f1, nrm));
            u32 h = pkbf(f1, f0);
            hb[i2] = h;
            lb[i2] = pkbf(f1 - bfhi(h), f0 - bflo(h));
        }
        uint4* hp = (uint4*)(hd + (b * NP + n) * DI);
        uint4* lp = (uint4*)(ld + (b * NP + n) * DI);
        #pragma unroll
        for (int i = 0; i < 4; i++) {
            hp[i] = make_uint4(hb[4*i], hb[4*i+1], hb[4*i+2], hb[4*i+3]);
            lp[i] = make_uint4(lb[4*i], lb[4*i+1], lb[4*i+2], lb[4*i+3]);
        }
        if (wg == 0) g_thn[b * NP + n] = nrm;
        else {
            unsigned mx = __reduce_max_sync(0xffffffffu, __float_as_uint(nrm));
            if ((wt & 31) == 0) atomicMax(&g_phimax[b], mx);
        }
    }
}

// ---------------------------------------------------------------------------
// Stage 2: mma.sync bf16x3 flash attention, split-K=2, bound-softmax.
// grid (100, SPL, BATCH), 128 threads (4 warps x m16).
// smem per buffer: Kh(64x80) Kl(64x80) Vh(32x144) Vl(32x144) = 19456B, x2 buf.
// ---------------------------------------------------------------------------
#define KROW 80
#define VROW 144
#define BUFB 19456
#define OFF_KL 5120
#define OFF_VH 10240
#define OFF_VL 14848

__global__ void __launch_bounds__(128) attn_kernel()
{
    __shared__ __align__(16) char smem[2 * BUFB];

    const int b = blockIdx.z, split = blockIdx.y;
    const int n0 = blockIdx.x * QB;
    const int tid = threadIdx.x, w = tid >> 5, lane = tid & 31;
    const int g = lane >> 2, t4 = lane & 3;
    const int q0 = n0 + w * 16 + g, q1 = q0 + 8;

    // prefetch one tile (all threads)
    auto prefetch = [&](int t, int buf) {
        const int k0 = split * KPS + t * KT;
        char* bb = smem + buf * BUFB;
        #pragma unroll
        for (int i = 0; i < 2; i++) {
            int c = tid + 128 * i;
            {   // K: 64 rows x 4 chunks
                int row = c >> 2, ci = c & 3;
                const int src = (b * NP + k0 + row) * DI + ci * 8;
                cpa16(bb + row * KROW + ci * 16, g_Kh + src);
                cpa16(bb + OFF_KL + row * KROW + ci * 16, g_Kl + src);
            }
            {   // V: 32 rows x 8 chunks
                int d = c >> 3, ci = c & 7;
                const int src = (b * DI + d) * NP + k0 + ci * 8;
                cpa16(bb + OFF_VH + d * VROW + ci * 16, g_Vh + src);
                cpa16(bb + OFF_VL + d * VROW + ci * 16, g_Vl + src);
            }
        }
        asm volatile("cp.async.commit_group;" ::: "memory");
    };

    // Q fragments from gmem (once)
    u32 ah[2][4], al[2][4];
    {
        const u32* Qh32 = (const u32*)g_Qh;
        const u32* Ql32 = (const u32*)g_Ql;
        const int r0 = (b * NP + q0) * (DI / 2), r1 = (b * NP + q1) * (DI / 2);
        #pragma unroll
        for (int s = 0; s < 2; s++) {
            ah[s][0] = Qh32[r0 + t4 + 8 * s];
            ah[s][1] = Qh32[r1 + t4 + 8 * s];
            ah[s][2] = Qh32[r0 + t4 + 4 + 8 * s];
            ah[s][3] = Qh32[r1 + t4 + 4 + 8 * s];
            al[s][0] = Ql32[r0 + t4 + 8 * s];
            al[s][1] = Ql32[r1 + t4 + 8 * s];
            al[s][2] = Ql32[r0 + t4 + 4 + 8 * s];
            al[s][3] = Ql32[r1 + t4 + 4 + 8 * s];
        }
    }
    const float pm = sqrtf(__uint_as_float(g_phimax[b]));
    const float bd0 = sqrtf(g_thn[b * NP + q0]) * pm;
    const float bd1 = sqrtf(g_thn[b * NP + q1]) * pm;

    float o[4][4];
    #pragma unroll
    for (int i = 0; i < 4; i++)
        #pragma unroll
        for (int j = 0; j < 4; j++) o[i][j] = 0.f;
    float l0 = 0.f, l1 = 0.f;

    prefetch(0, 0);

    for (int t = 0; t < NTL; t++) {
        if (t + 1 < NTL) {
            prefetch(t + 1, (t + 1) & 1);
            asm volatile("cp.async.wait_group 1;" ::: "memory");
        } else {
            asm volatile("cp.async.wait_group 0;" ::: "memory");
        }
        __syncthreads();

        const char* bb = smem + (t & 1) * BUFB;

        // ---- S = Q K^T (bf16x3) ----
        float sc[8][4];
        #pragma unroll
        for (int j = 0; j < 8; j++)
            #pragma unroll
            for (int i = 0; i < 4; i++) sc[j][i] = 0.f;

        #pragma unroll
        for (int s = 0; s < 2; s++) {
            #pragma unroll
            for (int j = 0; j < 8; j++) {
                const char* kb = bb + (8 * j + g) * KROW + 4 * t4 + 32 * s;
                u32 bh0 = *(const u32*)kb, bh1 = *(const u32*)(kb + 16);
                u32 bl0 = *(const u32*)(kb + OFF_KL), bl1 = *(const u32*)(kb + OFF_KL + 16);
                mma_bf16(sc[j], ah[s], bh0, bh1);
                mma_bf16(sc[j], al[s], bh0, bh1);
                mma_bf16(sc[j], ah[s], bl0, bl1);
            }
        }

        // ---- exp -> P fragments (hi/lo bf16), accumulate l ----
        u32 ph[4][4], pl[4][4];
        #pragma unroll
        for (int j = 0; j < 8; j++) {
            float p0 = __expf(sc[j][0] - bd0);
            float p1 = __expf(sc[j][1] - bd0);
            float p2 = __expf(sc[j][2] - bd1);
            float p3 = __expf(sc[j][3] - bd1);
            l0 += p0 + p1; l1 += p2 + p3;
            u32 h01 = pkbf(p1, p0), h23 = pkbf(p3, p2);
            u32 lo01 = pkbf(p1 - bfhi(h01), p0 - bflo(h01));
            u32 lo23 = pkbf(p3 - bfhi(h23), p2 - bflo(h23));
            const int s4 = j >> 1, hf = j & 1;
            ph[s4][2 * hf] = h01; ph[s4][2 * hf + 1] = h23;
            pl[s4][2 * hf] = lo01; pl[s4][2 * hf + 1] = lo23;
        }

        // ---- O += P V (bf16x3) ----
        #pragma unroll
        for (int s4 = 0; s4 < 4; s4++) {
            #pragma unroll
            for (int j2 = 0; j2 < 4; j2++) {
                const char* vb = bb + OFF_VH + (8 * j2 + g) * VROW + 4 * t4 + 32 * s4;
                u32 bh0 = *(const u32*)vb, bh1 = *(const u32*)(vb + 16);
                u32 bl0 = *(const u32*)(vb + (OFF_VL - OFF_VH));
                u32 bl1 = *(const u32*)(vb + (OFF_VL - OFF_VH) + 16);
                mma_bf16(o[j2], ph[s4], bh0, bh1);
                mma_bf16(o[j2], pl[s4], bh0, bh1);
                mma_bf16(o[j2], ph[s4], bl0, bl1);
            }
        }
        __syncthreads();
    }

    // reduce l across the 4 lanes sharing a row
    l0 += __shfl_xor_sync(0xffffffffu, l0, 1);
    l0 += __shfl_xor_sync(0xffffffffu, l0, 2);
    l1 += __shfl_xor_sync(0xffffffffu, l1, 1);
    l1 += __shfl_xor_sync(0xffffffffu, l1, 2);

    const int pb = (b * SPL + split) * NP;
    #pragma unroll
    for (int j2 = 0; j2 < 4; j2++) {
        *(float2*)(g_acc + (pb + q0) * DI + 8 * j2 + 2 * t4) = make_float2(o[j2][0], o[j2][1]);
        *(float2*)(g_acc + (pb + q1) * DI + 8 * j2 + 2 * t4) = make_float2(o[j2][2], o[j2][3]);
    }
    if (t4 == 0) { g_lp[pb + q0] = l0; g_lp[pb + q1] = l1; }
}

// ---------------------------------------------------------------------------
// Stage 3: merge split partials + output projection + residual.
// grid (50, BATCH), 128 threads, thread = 1 position.
// ---------------------------------------------------------------------------
__global__ void __launch_bounds__(128) merge_kernel(
    const float* __restrict__ x,
    const float* __restrict__ w_w,
    float* __restrict__ out)
{
    __shared__ __align__(16) float ws[CH * DI];
    const int b = blockIdx.y, tid = threadIdx.x;
    const int n = blockIdx.x * 128 + tid;

    for (int i = tid; i < CH * DI; i += 128) ws[i] = w_w[i];
    __syncthreads();

    const float l = g_lp[(b * SPL) * NP + n] + g_lp[(b * SPL + 1) * NP + n];
    const float inv = 1.f / l;
    const float* a0 = g_acc + ((b * SPL) * NP + n) * DI;
    const float* a1 = g_acc + ((b * SPL + 1) * NP + n) * DI;

    u64 y2[16];
    #pragma unroll
    for (int i2 = 0; i2 < 16; i2++) {
        float e0 = (a0[2 * i2] + a1[2 * i2]) * inv;
        float e1 = (a0[2 * i2 + 1] + a1[2 * i2 + 1]) * inv;
        asm("mov.b64 %0,{%1,%2};" : "=l"(y2[i2]) : "f"(e0), "f"(e1));
    }

    const float* xb = x + b * CH * NP + n;
    float* ob = out + b * CH * NP + n;
    #pragma unroll 2
    for (int c = 0; c < CH; c++) {
        const u64* w2 = (const u64*)(ws + c * DI);
        u64 o2 = 0ull;
        #pragma unroll
        for (int i2 = 0; i2 < 16; i2++) o2 = f2fma(w2[i2], y2[i2], o2);
        ob[c * NP] = xb[c * NP] + f2hadd(o2);
    }
}

// ---------------------------------------------------------------------------
extern "C" void kernel_launch(void* const* d_in, const int* in_sizes, int n_in,
                              void* d_out, int out_size)
{
    const float* x       = (const float*)d_in[0];
    const float* gw      = (const float*)d_in[1];
    const float* theta_w = (const float*)d_in[2];
    const float* phi_w   = (const float*)d_in[3];
    const float* w_w     = (const float*)d_in[4];
    float* out           = (float*)d_out;

    void* pm = nullptr;
    cudaGetSymbolAddress(&pm, g_phimax);
    cudaMemsetAsync(pm, 0, sizeof(unsigned) * BATCH);

    dim3 gp(NP / 128, BATCH);
    proj_kernel<<<gp, PT>>>(x, theta_w, phi_w, gw);

    dim3 ga(NP / QB, SPL, BATCH);
    attn_kernel<<<ga, 128>>>();

    merge_kernel<<<gp, 128>>>(x, w_w, out);
}

// round 6
// speedup vs baseline: 3.0533x; 1.1824x over previous
#include <cuda_runtime.h>
#include <cuda_bf16.h>
#include <cstdint>

#define BATCH 2
#define CH 64
#define DI 32
#define NP 6400
#define SPL 3
#define KT 64
#define QB 64

typedef uint32_t u32;
typedef unsigned long long u64;

#define LOG2E 1.4426950408889634f

// ---------------- scratch ----------------
__device__ __nv_bfloat16 g_Qh[BATCH * NP * DI], g_Ql[BATCH * NP * DI];
__device__ __nv_bfloat16 g_Kh[BATCH * NP * DI], g_Kl[BATCH * NP * DI];
__device__ __nv_bfloat16 g_Vh[BATCH * DI * NP], g_Vl[BATCH * DI * NP]; // [b][d][n]
__device__ float g_thn[BATCH * NP];
__device__ unsigned g_phimax[BATCH];
__device__ float g_acc[BATCH * SPL * NP * DI];
__device__ float g_lp[BATCH * SPL * NP];

// ---------------- helpers ----------------
__device__ __forceinline__ u64 f2fma(u64 a, u64 b, u64 c) {
    u64 d; asm("fma.rn.f32x2 %0,%1,%2,%3;" : "=l"(d) : "l"(a), "l"(b), "l"(c)); return d;
}
__device__ __forceinline__ float f2hadd(u64 a) {
    float lo, hi; asm("mov.b64 {%0,%1},%2;" : "=f"(lo), "=f"(hi) : "l"(a)); return lo + hi;
}
__device__ __forceinline__ u32 pkbf(float hi, float lo) {
    u32 r; asm("cvt.rn.bf16x2.f32 %0,%1,%2;" : "=r"(r) : "f"(hi), "f"(lo)); return r;
}
__device__ __forceinline__ float bflo(u32 p) { return __uint_as_float(p << 16); }
__device__ __forceinline__ float bfhi(u32 p) { return __uint_as_float(p & 0xffff0000u); }
__device__ __forceinline__ float ex2f(float x) {
    float r; asm("ex2.approx.f32 %0,%1;" : "=f"(r) : "f"(x)); return r;
}
__device__ __forceinline__ void mma_bf16(float* c, const u32* a, u32 b0, u32 b1) {
    asm("mma.sync.aligned.m16n8k16.row.col.f32.bf16.bf16.f32 "
        "{%0,%1,%2,%3},{%4,%5,%6,%7},{%8,%9},{%0,%1,%2,%3};"
        : "+f"(c[0]), "+f"(c[1]), "+f"(c[2]), "+f"(c[3])
        : "r"(a[0]), "r"(a[1]), "r"(a[2]), "r"(a[3]), "r"(b0), "r"(b1));
}
__device__ __forceinline__ void cpa16(u32 sa, const void* g) {
    asm volatile("cp.async.cg.shared.global [%0],[%1],16;" :: "r"(sa), "l"(g) : "memory");
}
__device__ __forceinline__ u32 smaddr(const void* p) {
    u32 a; asm("{ .reg .u64 t; cvta.to.shared.u64 t,%1; cvt.u32.u64 %0,t; }" : "=r"(a) : "l"(p));
    return a;
}

// ---------------------------------------------------------------------------
// Stage 1: projection. wg0=theta(+log2e scale), wg1=phi, wg2=g->V^T (coalesced).
// ---------------------------------------------------------------------------
#define PT 384
__global__ void __launch_bounds__(PT) proj_kernel(
    const float* __restrict__ x,
    const float* __restrict__ theta_w,
    const float* __restrict__ phi_w,
    const float* __restrict__ gw)
{
    __shared__ __align__(16) float xs[CH * 128];
    __shared__ __align__(16) float wsT[3 * CH * DI];

    const int b = blockIdx.y, n0 = blockIdx.x * 128, tid = threadIdx.x;
    const int wg = tid >> 7, wt = tid & 127;
    const float* wsrc = (wg == 0) ? theta_w : (wg == 1) ? phi_w : gw;

    for (int idx = wt; idx < DI * CH; idx += 128) {
        int i = idx / CH, c = idx % CH;
        wsT[wg * CH * DI + c * DI + i] = wsrc[idx];
    }
    const float* xb = x + b * CH * NP + n0;
    for (int idx = tid; idx < CH * 128; idx += PT)
        xs[idx] = xb[(idx >> 7) * NP + (idx & 127)];
    __syncthreads();

    u64 acc2[16];
    #pragma unroll
    for (int i = 0; i < 16; i++) acc2[i] = 0ull;
    const float* wp = wsT + wg * CH * DI;
    #pragma unroll 4
    for (int c = 0; c < CH; c++) {
        float xv = xs[c * 128 + wt];
        u64 x2; asm("mov.b64 %0,{%1,%1};" : "=l"(x2) : "f"(xv));
        const u64* w2 = (const u64*)(wp + c * DI);
        #pragma unroll
        for (int i2 = 0; i2 < 16; i2++) acc2[i2] = f2fma(w2[i2], x2, acc2[i2]);
    }
    float v[DI];
    #pragma unroll
    for (int i2 = 0; i2 < 16; i2++)
        asm("mov.b64 {%0,%1},%2;" : "=f"(v[2 * i2]), "=f"(v[2 * i2 + 1]) : "l"(acc2[i2]));

    const int n = n0 + wt;
    if (wg < 2) {
        if (wg == 0) {
            #pragma unroll
            for (int i = 0; i < DI; i++) v[i] *= LOG2E;   // exp2 pre-scale
        }
        __nv_bfloat16* hd = (wg == 0) ? g_Qh : g_Kh;
        __nv_bfloat16* ld = (wg == 0) ? g_Ql : g_Kl;
        float nrm = 0.f;
        u32 hb[16], lb[16];
        #pragma unroll
        for (int i2 = 0; i2 < 16; i2++) {
            float f0 = v[2 * i2], f1 = v[2 * i2 + 1];
            nrm = fmaf(f0, f0, fmaf(f1, f1, nrm));
            u32 h = pkbf(f1, f0);
            hb[i2] = h;
            lb[i2] = pkbf(f1 - bfhi(h), f0 - bflo(h));
        }
        uint4* hp = (uint4*)(hd + (b * NP + n) * DI);
        uint4* lp = (uint4*)(ld + (b * NP + n) * DI);
        #pragma unroll
        for (int i = 0; i < 4; i++) {
            hp[i] = make_uint4(hb[4*i], hb[4*i+1], hb[4*i+2], hb[4*i+3]);
            lp[i] = make_uint4(lb[4*i], lb[4*i+1], lb[4*i+2], lb[4*i+3]);
        }
        if (wg == 0) g_thn[b * NP + n] = nrm;
        else {
            unsigned mx = __reduce_max_sync(0xffffffffu, __float_as_uint(nrm));
            if ((wt & 31) == 0) atomicMax(&g_phimax[b], mx);
        }
    }
    __syncthreads();          // all xs reads done
    __nv_bfloat16* vh = (__nv_bfloat16*)xs;       // 8KB
    __nv_bfloat16* vl = vh + 32 * 128;            // 8KB
    if (wg == 2) {
        #pragma unroll
        for (int i = 0; i < DI; i++) {
            __nv_bfloat16 h = __float2bfloat16(v[i]);
            vh[i * 128 + wt] = h;
            vl[i * 128 + wt] = __float2bfloat16(v[i] - __bfloat162float(h));
        }
    }
    __syncthreads();
    // coalesced copy-out: 2 arrays x 32 rows x 16 uint4
    for (int idx = tid; idx < 1024; idx += PT) {
        int arr = idx >> 9, rem = idx & 511, d = rem >> 4, ch = rem & 15;
        uint4 val = ((const uint4*)(arr ? vl : vh))[rem];
        __nv_bfloat16* dst = (arr ? g_Vl : g_Vh) + (b * DI + d) * NP + n0;
        ((uint4*)dst)[ch] = val;
    }
}

// ---------------------------------------------------------------------------
// Stage 2: bf16x3 mma.sync flash attention, SPL=3, bound-softmax (exp2).
// grid (100, 3, 2) = 600 CTAs, 128 thr, 4 CTAs/SM.
// ---------------------------------------------------------------------------
#define KROW 80
#define VROW 144
#define BUFB 19456
#define OFF_KL 5120
#define OFF_VH 10240
#define OFF_VL 14848

__global__ void __launch_bounds__(128, 4) attn_kernel()
{
    __shared__ __align__(16) char smem[2 * BUFB];

    const int b = blockIdx.z, split = blockIdx.y;
    const int n0 = blockIdx.x * QB;
    const int tid = threadIdx.x, w = tid >> 5, lane = tid & 31;
    const int g = lane >> 2, t4 = lane & 3;
    const int q0 = n0 + w * 16 + g, q1 = q0 + 8;

    const int t0  = split * 33 + (split > 0 ? 1 : 0);   // 0, 34, 67
    const int ntl = 34 - (split > 0 ? 1 : 0);           // 34, 33, 33
    const int k0s = t0 * KT;

    // hoisted prefetch state
    const u32 smbase = smaddr(smem);
    u32 koff[2], voff[2];
    const __nv_bfloat16 *khp[2], *klp[2], *vhp[2], *vlp[2];
    #pragma unroll
    for (int i = 0; i < 2; i++) {
        int c = tid + 128 * i;
        int row = c >> 2, kci = c & 3;
        koff[i] = row * KROW + kci * 16;
        khp[i] = g_Kh + (b * NP + k0s + row) * DI + kci * 8;
        klp[i] = g_Kl + (b * NP + k0s + row) * DI + kci * 8;
        int d = c >> 3, vci = c & 7;
        voff[i] = d * VROW + vci * 16;
        vhp[i] = g_Vh + (b * DI + d) * NP + k0s + vci * 8;
        vlp[i] = g_Vl + (b * DI + d) * NP + k0s + vci * 8;
    }
    auto prefetch = [&](int buf) {
        const u32 bb = smbase + buf * BUFB;
        #pragma unroll
        for (int i = 0; i < 2; i++) {
            cpa16(bb + koff[i], khp[i]);
            cpa16(bb + OFF_KL + koff[i], klp[i]);
            cpa16(bb + OFF_VH + voff[i], vhp[i]);
            cpa16(bb + OFF_VL + voff[i], vlp[i]);
            khp[i] += KT * DI; klp[i] += KT * DI;
            vhp[i] += KT;      vlp[i] += KT;
        }
        asm volatile("cp.async.commit_group;" ::: "memory");
    };

    // Q fragments
    u32 ah[2][4], al[2][4];
    {
        const u32* Qh32 = (const u32*)g_Qh;
        const u32* Ql32 = (const u32*)g_Ql;
        const int r0 = (b * NP + q0) * (DI / 2), r1 = (b * NP + q1) * (DI / 2);
        #pragma unroll
        for (int s = 0; s < 2; s++) {
            ah[s][0] = Qh32[r0 + t4 + 8 * s];
            ah[s][1] = Qh32[r1 + t4 + 8 * s];
            ah[s][2] = Qh32[r0 + t4 + 4 + 8 * s];
            ah[s][3] = Qh32[r1 + t4 + 4 + 8 * s];
            al[s][0] = Ql32[r0 + t4 + 8 * s];
            al[s][1] = Ql32[r1 + t4 + 8 * s];
            al[s][2] = Ql32[r0 + t4 + 4 + 8 * s];
            al[s][3] = Ql32[r1 + t4 + 4 + 8 * s];
        }
    }
    const float pm = sqrtf(__uint_as_float(g_phimax[b]));
    const float bd0 = sqrtf(g_thn[b * NP + q0]) * pm;
    const float bd1 = sqrtf(g_thn[b * NP + q1]) * pm;

    float o[4][4];
    #pragma unroll
    for (int i = 0; i < 4; i++)
        #pragma unroll
        for (int j = 0; j < 4; j++) o[i][j] = 0.f;
    float l0 = 0.f, l1 = 0.f;

    prefetch(0);

    for (int t = 0; t < ntl; t++) {
        if (t + 1 < ntl) {
            prefetch((t + 1) & 1);
            asm volatile("cp.async.wait_group 1;" ::: "memory");
        } else {
            asm volatile("cp.async.wait_group 0;" ::: "memory");
        }
        __syncthreads();

        const char* bb = smem + (t & 1) * BUFB;

        // ---- S = Q K^T (bf16x3) ----
        float sc[8][4];
        #pragma unroll
        for (int j = 0; j < 8; j++)
            #pragma unroll
            for (int i = 0; i < 4; i++) sc[j][i] = 0.f;
        #pragma unroll
        for (int s = 0; s < 2; s++) {
            #pragma unroll
            for (int j = 0; j < 8; j++) {
                const char* kb = bb + (8 * j + g) * KROW + 4 * t4 + 32 * s;
                u32 bh0 = *(const u32*)kb, bh1 = *(const u32*)(kb + 16);
                u32 bl0 = *(const u32*)(kb + OFF_KL), bl1 = *(const u32*)(kb + OFF_KL + 16);
                mma_bf16(sc[j], ah[s], bh0, bh1);
                mma_bf16(sc[j], al[s], bh0, bh1);
                mma_bf16(sc[j], ah[s], bl0, bl1);
            }
        }

        // ---- exp2 -> P (hi/lo), accumulate l ----
        u32 ph[4][4], pl[4][4];
        #pragma unroll
        for (int j = 0; j < 8; j++) {
            float p0 = ex2f(sc[j][0] - bd0);
            float p1 = ex2f(sc[j][1] - bd0);
            float p2 = ex2f(sc[j][2] - bd1);
            float p3 = ex2f(sc[j][3] - bd1);
            l0 += p0 + p1; l1 += p2 + p3;
            u32 h01 = pkbf(p1, p0), h23 = pkbf(p3, p2);
            u32 lo01 = pkbf(p1 - bfhi(h01), p0 - bflo(h01));
            u32 lo23 = pkbf(p3 - bfhi(h23), p2 - bflo(h23));
            const int s4 = j >> 1, hf = j & 1;
            ph[s4][2 * hf] = h01; ph[s4][2 * hf + 1] = h23;
            pl[s4][2 * hf] = lo01; pl[s4][2 * hf + 1] = lo23;
        }

        // ---- O += P V (bf16x3) ----
        #pragma unroll
        for (int s4 = 0; s4 < 4; s4++) {
            #pragma unroll
            for (int j2 = 0; j2 < 4; j2++) {
                const char* vb = bb + OFF_VH + (8 * j2 + g) * VROW + 4 * t4 + 32 * s4;
                u32 bh0 = *(const u32*)vb, bh1 = *(const u32*)(vb + 16);
                u32 bl0 = *(const u32*)(vb + (OFF_VL - OFF_VH));
                u32 bl1 = *(const u32*)(vb + (OFF_VL - OFF_VH) + 16);
                mma_bf16(o[j2], ph[s4], bh0, bh1);
                mma_bf16(o[j2], pl[s4], bh0, bh1);
                mma_bf16(o[j2], ph[s4], bl0, bl1);
            }
        }
        __syncthreads();
    }

    l0 += __shfl_xor_sync(0xffffffffu, l0, 1);
    l0 += __shfl_xor_sync(0xffffffffu, l0, 2);
    l1 += __shfl_xor_sync(0xffffffffu, l1, 1);
    l1 += __shfl_xor_sync(0xffffffffu, l1, 2);

    const int pb = (b * SPL + split) * NP;
    #pragma unroll
    for (int j2 = 0; j2 < 4; j2++) {
        *(float2*)(g_acc + (pb + q0) * DI + 8 * j2 + 2 * t4) = make_float2(o[j2][0], o[j2][1]);
        *(float2*)(g_acc + (pb + q1) * DI + 8 * j2 + 2 * t4) = make_float2(o[j2][2], o[j2][3]);
    }
    if (t4 == 0) { g_lp[pb + q0] = l0; g_lp[pb + q1] = l1; }
}

// ---------------------------------------------------------------------------
// Stage 3: merge 3 partials + output projection + residual.
// ---------------------------------------------------------------------------
__global__ void __launch_bounds__(128) merge_kernel(
    const float* __restrict__ x,
    const float* __restrict__ w_w,
    float* __restrict__ out)
{
    __shared__ __align__(16) float ws[CH * DI];
    const int b = blockIdx.y, tid = threadIdx.x;
    const int n = blockIdx.x * 128 + tid;

    for (int i = tid; i < CH * DI; i += 128) ws[i] = w_w[i];
    __syncthreads();

    float l = 0.f;
    #pragma unroll
    for (int s = 0; s < SPL; s++) l += g_lp[(b * SPL + s) * NP + n];
    const float inv = 1.f / l;

    const float* a0 = g_acc + ((b * SPL + 0) * NP + n) * DI;
    const float* a1 = g_acc + ((b * SPL + 1) * NP + n) * DI;
    const float* a2 = g_acc + ((b * SPL + 2) * NP + n) * DI;

    u64 y2[16];
    #pragma unroll
    for (int i2 = 0; i2 < 16; i2++) {
        float e0 = (a0[2 * i2] + a1[2 * i2] + a2[2 * i2]) * inv;
        float e1 = (a0[2 * i2 + 1] + a1[2 * i2 + 1] + a2[2 * i2 + 1]) * inv;
        asm("mov.b64 %0,{%1,%2};" : "=l"(y2[i2]) : "f"(e0), "f"(e1));
    }

    const float* xb = x + b * CH * NP + n;
    float* ob = out + b * CH * NP + n;
    #pragma unroll 2
    for (int c = 0; c < CH; c++) {
        const u64* w2 = (const u64*)(ws + c * DI);
        u64 o2 = 0ull;
        #pragma unroll
        for (int i2 = 0; i2 < 16; i2++) o2 = f2fma(w2[i2], y2[i2], o2);
        ob[c * NP] = xb[c * NP] + f2hadd(o2);
    }
}

// ---------------------------------------------------------------------------
extern "C" void kernel_launch(void* const* d_in, const int* in_sizes, int n_in,
                              void* d_out, int out_size)
{
    const float* x       = (const float*)d_in[0];
    const float* gw      = (const float*)d_in[1];
    const float* theta_w = (const float*)d_in[2];
    const float* phi_w   = (const float*)d_in[3];
    const float* w_w     = (const float*)d_in[4];
    float* out           = (float*)d_out;

    void* pm = nullptr;
    cudaGetSymbolAddress(&pm, g_phimax);
    cudaMemsetAsync(pm, 0, sizeof(unsigned) * BATCH);

    dim3 gp(NP / 128, BATCH);
    proj_kernel<<<gp, PT>>>(x, theta_w, phi_w, gw);

    dim3 ga(NP / QB, SPL, BATCH);
    attn_kernel<<<ga, 128>>>();

    merge_kernel<<<gp, 128>>>(x, w_w, out);
}